// round 7
// baseline (speedup 1.0000x reference)
#include <cuda_runtime.h>

// Guided filter r=3, fused, tile 32x35, 5 CTAs/SM (42.3KB smem, <=51 regs).
// H1b re-reads pB (no vp/vIp rings) to fit the register budget.

#define NT 256
#define WD 1024
#define HD 1024
#define HWC (1024 * 1024)
#define TW 32
#define TH 35
#define ABR 41            // TH + 6
#define VP2 45            // pA/pB pitch in float2
#define MP2 39            // M pitch in float2 (38 cols used)
#define HP2 33            // pH pitch in float2 (32 cols used)
#define INV49 (1.0f / 49.0f)
#define EPS_GF 1e-6f

#define OFF_PB 0
#define OFF_PA (ABR * VP2)            // 1845 (also pH)
#define OFF_M  (2 * ABR * VP2)        // 3690
#define N_F2   (2 * ABR * VP2 + ABR * MP2)   // 3690 + 1599 = 5289
#define SMEM_BYTES (N_F2 * 8)                // 42312 -> 5 CTAs/SM

__global__ void __launch_bounds__(NT, 5)
gf_kernel(const float* __restrict__ gI,
          const float* __restrict__ gP,
          float* __restrict__ gOut) {
    extern __shared__ float2 sm2[];
    float2* pB = sm2 + OFF_PB;     // (vp, vIp) vertical 7-sums
    float2* pA = sm2 + OFF_PA;     // (vI, vII) vertical 7-sums (ch0 only)
    float2* pH = sm2 + OFF_PA;     // (hsA, hsB) — aliases pA after H1a
    float2* M  = sm2 + OFF_M;      // (mean_I, 1/(var+eps)) per ab-pixel

    const int tid = threadIdx.x;
    const int bx = blockIdx.x, by = blockIdx.y, bz = blockIdx.z;
    const int x0 = bx * TW, y0 = by * TH;
    const float* Ib = gI + (size_t)bz * HWC;

#pragma unroll
    for (int ch = 0; ch < 3; ch++) {
        const float* Pb = gP + ((size_t)bz * 3 + ch) * HWC;

        // ---------- V1: vertical 7-sums of {p, I*p} (+ {I,I*I} on ch0) ----
        // thread = (segment 0..4, v-col 0..43); 9 ab-rows per segment
        if (tid < 220) {
            int seg = tid / 44;
            int vx  = tid - seg * 44;
            int gxv = x0 + vx - 6;
            bool xok = (unsigned)gxv < (unsigned)WD;
            int gyr0 = y0 + seg * 9 - 6;
            int ya0 = seg * 9;
            float iv7[7], pv7[7];
            float sI = 0.f, sII = 0.f, sp = 0.f, sIp = 0.f;
#pragma unroll
            for (int k = 0; k < 7; k++) { iv7[k] = 0.f; pv7[k] = 0.f; }
#pragma unroll
            for (int t = 0; t < 15; t++) {
                int gyr = gyr0 + t;
                float iv = 0.f, pv = 0.f;
                if (xok && (unsigned)gyr < (unsigned)HD) {
                    int off = gyr * WD + gxv;
                    iv = Ib[off];
                    pv = Pb[off];
                }
                int k = t % 7;
                float oi = iv7[k], oq = pv7[k];
                if (ch == 0) {
                    sI  += iv - oi;
                    sII += iv * iv - oi * oi;
                }
                sp  += pv - oq;
                sIp += iv * pv - oi * oq;
                iv7[k] = iv; pv7[k] = pv;
                if (t >= 6) {
                    int ar = ya0 + t - 6;
                    if (ar < ABR) {
                        if (ch == 0) pA[ar * VP2 + vx] = make_float2(sI, sII);
                        pB[ar * VP2 + vx] = make_float2(sp, sIp);
                    }
                }
            }
        }
        __syncthreads();

        // ---------- H1a (ch0 only): h-sums of (vI,vII) -> (mi, rv) --------
        if (ch == 0) {
            // thread = (chunk 0..4 of 8 ax, row 0..40); tid < 205
            if (tid < 205) {
                int c  = tid / ABR;
                int ya = tid - c * ABR;
                int axb = c * 8;
                int row = ya * VP2;
                float w0[7], w1[7];
                float s0 = 0.f, s1 = 0.f;
#pragma unroll
                for (int k = 0; k < 7; k++) { w0[k] = 0.f; w1[k] = 0.f; }
#pragma unroll
                for (int t = 0; t < 14; t++) {
                    int vx = axb + t;
                    float2 A = (vx < 44) ? pA[row + vx] : make_float2(0.f, 0.f);
                    int k = t % 7;
                    s0 += A.x - w0[k]; s1 += A.y - w1[k];
                    w0[k] = A.x; w1[k] = A.y;
                    if (t >= 6) {
                        int ax = axb + t - 6;
                        if (ax < 38) {
                            float mi  = s0 * INV49;
                            float var = fmaf(s1, INV49, -mi * mi);
                            M[ya * MP2 + ax] =
                                make_float2(mi, __fdividef(1.0f, var + EPS_GF));
                        }
                    }
                }
            }
            __syncthreads();
        }

        // ---------- H1b: h-sums of (vp,vIp) -> a,b -> h-sums of a,b -------
        // thread = (chunk 0..4 of 7 out-x, row 0..40); tid < 205
        // (vp,vIp) window via pB re-read at vx-7 (no rings -> fits 51 regs)
        if (tid < 205) {
            int c  = tid / ABR;
            int ya = tid - c * ABR;
            int oxb = c * 7;
            int gya = y0 + ya - 3;
            bool yok = (unsigned)gya < (unsigned)HD;
            int rowB = ya * VP2, rowM = ya * MP2, rowH = ya * HP2;
            float wa[7], wb[7];
            float s2 = 0.f, s3 = 0.f, sA = 0.f, sB = 0.f;
#pragma unroll
            for (int k = 0; k < 7; k++) { wa[k] = 0.f; wb[k] = 0.f; }
#pragma unroll
            for (int t = 0; t < 19; t++) {
                int vx = oxb + t;
                float2 Bn = (vx < 44) ? pB[rowB + vx] : make_float2(0.f, 0.f);
                s2 += Bn.x; s3 += Bn.y;
                if (t >= 7) {
                    float2 Bo = pB[rowB + vx - 7];
                    s2 -= Bo.x; s3 -= Bo.y;
                }
                if (t >= 6) {
                    int ax = oxb + t - 6;            // a-index, gx = x0+ax-3
                    float av = 0.f, bv = 0.f;
                    if (yok && (unsigned)(x0 + ax - 3) < (unsigned)WD) {
                        float2 m = M[rowM + ax];
                        float mp  = s2 * INV49;
                        float mip = s3 * INV49;
                        av = (mip - m.x * mp) * m.y;
                        bv = fmaf(-av, m.x, mp);
                    }
                    int k = t % 7;
                    sA += av - wa[k]; sB += bv - wb[k];
                    wa[k] = av; wb[k] = bv;
                    if (t >= 12) {
                        int ox = oxb + t - 12;
                        if (ox < 32)
                            pH[rowH + ox] = make_float2(sA, sB);
                    }
                }
            }
        }
        __syncthreads();

        // ---------- V2: vertical 7-sum of hs + combine + store ------------
        // thread = (out-x 0..31, segment 0..7); 5 out rows per segment
        {
            int ox  = tid & 31;
            int seg = tid >> 5;
            int ya0 = seg * 5;
            float wa[7], wb[7];
            float sA = 0.f, sB = 0.f;
#pragma unroll
            for (int k = 0; k < 7; k++) { wa[k] = 0.f; wb[k] = 0.f; }
            const int gx = x0 + ox;
            float* Ob = gOut + ((size_t)bz * 3 + ch) * HWC;
#pragma unroll
            for (int t = 0; t < 11; t++) {
                int ar = ya0 + t;
                float2 h = (ar < ABR) ? pH[ar * HP2 + ox]
                                      : make_float2(0.f, 0.f);
                int k = t % 7;
                sA += h.x - wa[k]; sB += h.y - wb[k];
                wa[k] = h.x; wb[k] = h.y;
                if (t >= 6) {
                    int oy = ya0 + t - 6;
                    int gy = y0 + oy;
                    if (oy < TH && gy < HD) {
                        int off = gy * WD + gx;
                        float q = fmaf(sA * INV49, Ib[off], sB * INV49);
                        q = fminf(fmaxf(q, 0.0f), 1.0f);
                        Ob[off] = q;
                    }
                }
            }
        }
        // No trailing sync: V2 reads pH; next V1 writes only pB (disjoint),
        // and the next post-V1 barrier orders the following pH overwrite.
    }
}

extern "C" void kernel_launch(void* const* d_in, const int* in_sizes, int n_in,
                              void* d_out, int out_size) {
    const float* I = (const float*)d_in[0];
    const float* p = (const float*)d_in[1];
    if (n_in >= 2 && in_sizes[0] > in_sizes[1]) {  // defensive: I is smaller
        const float* t = I; I = p; p = t;
    }
    float* out = (float*)d_out;

    cudaFuncSetAttribute(gf_kernel,
                         cudaFuncAttributeMaxDynamicSharedMemorySize, SMEM_BYTES);
    dim3 grid(WD / TW, (HD + TH - 1) / TH, 8);
    gf_kernel<<<grid, NT, SMEM_BYTES>>>(I, p, out);
}

// round 10
// speedup vs baseline: 1.1152x; 1.1152x over previous
#include <cuda_runtime.h>

// Guided filter r=3, fused, tile 32x45, 4 CTAs/SM (52.6KB smem).
// R6 architecture (H1a/H1b split, pH aliases pA only after pA is dead)
// + interior-tile fast path (no bounds predication on ~86% of tiles).

#define NT 256
#define WD 1024
#define HD 1024
#define HWC (1024 * 1024)
#define TW 32
#define TH 45
#define ABR 51            // TH + 6
#define VP2 45            // pA/pB pitch in float2
#define MP2 39            // M pitch in float2 (38 cols used)
#define HP2 33            // pH pitch in float2 (32 cols used)
#define INV49 (1.0f / 49.0f)
#define EPS_GF 1e-6f

#define OFF_PB 0
#define OFF_PA (ABR * VP2)            // 2295 (also pH)
#define OFF_M  (2 * ABR * VP2)        // 4590
#define N_F2   (2 * ABR * VP2 + ABR * MP2)   // 4590 + 1989 = 6579
#define SMEM_BYTES (N_F2 * 8)                // 52632 -> 4 CTAs/SM

template<bool INTERIOR>
__device__ __forceinline__ void gf_tile(float2* __restrict__ sm2,
                                        const float* __restrict__ Ib,
                                        const float* __restrict__ gPz,
                                        float* __restrict__ gOz,
                                        int x0, int y0, int tid) {
    float2* pB = sm2 + OFF_PB;     // (vp, vIp) vertical 7-sums
    float2* pA = sm2 + OFF_PA;     // (vI, vII) vertical 7-sums (ch0 only)
    float2* pH = sm2 + OFF_PA;     // (hsA, hsB) — aliases pA after H1a
    float2* M  = sm2 + OFF_M;      // (mean_I, 1/(var+eps)) per a-pixel

#pragma unroll
    for (int ch = 0; ch < 3; ch++) {
        const float* Pb = gPz + (size_t)ch * HWC;

        // ---------- V1: vertical 7-sums of {p, I*p} (+ {I,I*I} on ch0) ----
        // thread = (segment 0..4, v-col 0..43); 11 ab-rows per segment
        if (tid < 220) {
            int seg = tid / 44;
            int vx  = tid - seg * 44;
            int gxv = x0 + vx - 6;
            bool xok = INTERIOR || (unsigned)gxv < (unsigned)WD;
            int gyr0 = y0 + seg * 11 - 6;
            int ya0 = seg * 11;
            float iv7[7], pv7[7];
            float sI = 0.f, sII = 0.f, sp = 0.f, sIp = 0.f;
#pragma unroll
            for (int k = 0; k < 7; k++) { iv7[k] = 0.f; pv7[k] = 0.f; }
#pragma unroll
            for (int t = 0; t < 17; t++) {
                int gyr = gyr0 + t;
                float iv, pv;
                if (INTERIOR) {
                    int off = gyr * WD + gxv;
                    iv = Ib[off];
                    pv = Pb[off];
                } else {
                    iv = 0.f; pv = 0.f;
                    if (xok && (unsigned)gyr < (unsigned)HD) {
                        int off = gyr * WD + gxv;
                        iv = Ib[off];
                        pv = Pb[off];
                    }
                }
                int k = t % 7;
                float oi = iv7[k], oq = pv7[k];
                if (ch == 0) {
                    sI  += iv - oi;
                    sII += iv * iv - oi * oi;
                }
                sp  += pv - oq;
                sIp += iv * pv - oi * oq;
                iv7[k] = iv; pv7[k] = pv;
                if (t >= 6) {
                    int ar = ya0 + t - 6;
                    if (ar < ABR) {
                        if (ch == 0) pA[ar * VP2 + vx] = make_float2(sI, sII);
                        pB[ar * VP2 + vx] = make_float2(sp, sIp);
                    }
                }
            }
        }
        __syncthreads();

        // ---------- H1a (ch0 only): h-sums of (vI,vII) -> (mi, rv) --------
        if (ch == 0) {
            // thread = (chunk 0..3 of 10 ax, row 0..50); tid < 204
            if (tid < 204) {
                int c  = tid / ABR;
                int ya = tid - c * ABR;
                int axb = c * 10;
                int row = ya * VP2;
                float w0[7], w1[7];
                float s0 = 0.f, s1 = 0.f;
#pragma unroll
                for (int k = 0; k < 7; k++) { w0[k] = 0.f; w1[k] = 0.f; }
#pragma unroll
                for (int t = 0; t < 16; t++) {
                    int vx = axb + t;
                    float2 A = (vx < 44) ? pA[row + vx] : make_float2(0.f, 0.f);
                    int k = t % 7;
                    s0 += A.x - w0[k]; s1 += A.y - w1[k];
                    w0[k] = A.x; w1[k] = A.y;
                    if (t >= 6) {
                        int ax = axb + t - 6;
                        if (ax < 38) {
                            float mi  = s0 * INV49;
                            float var = fmaf(s1, INV49, -mi * mi);
                            M[ya * MP2 + ax] =
                                make_float2(mi, __fdividef(1.0f, var + EPS_GF));
                        }
                    }
                }
            }
            __syncthreads();
        }

        // ---------- H1b: h-sums of (vp,vIp) -> a,b -> h-sums of a,b -------
        // thread = (chunk 0..3 of 8 out-x, row 0..50); tid < 204
        if (tid < 204) {
            int c  = tid / ABR;
            int ya = tid - c * ABR;
            int oxb = c * 8;
            int gya = y0 + ya - 3;
            bool yok = INTERIOR || (unsigned)gya < (unsigned)HD;
            int rowB = ya * VP2, rowM = ya * MP2, rowH = ya * HP2;
            float wp[7], wq[7], wa[7], wb[7];
            float s2 = 0.f, s3 = 0.f, sA = 0.f, sB = 0.f;
#pragma unroll
            for (int k = 0; k < 7; k++) {
                wp[k] = 0.f; wq[k] = 0.f; wa[k] = 0.f; wb[k] = 0.f;
            }
#pragma unroll
            for (int t = 0; t < 20; t++) {
                int vx = oxb + t;                    // <= 43: always valid
                float2 B = pB[rowB + vx];
                int k = t % 7;
                s2 += B.x - wp[k]; s3 += B.y - wq[k];
                wp[k] = B.x; wq[k] = B.y;
                if (t >= 6) {
                    int ax = oxb + t - 6;            // a-index, gx = x0+ax-3
                    float av, bv;
                    if (INTERIOR || (yok && (unsigned)(x0 + ax - 3) < (unsigned)WD)) {
                        float2 m = M[rowM + ax];
                        float mp  = s2 * INV49;
                        float mip = s3 * INV49;
                        av = (mip - m.x * mp) * m.y;
                        bv = fmaf(-av, m.x, mp);
                    } else {
                        av = 0.f; bv = 0.f;
                    }
                    sA += av - wa[k]; sB += bv - wb[k];
                    wa[k] = av; wb[k] = bv;
                    if (t >= 12)
                        pH[rowH + (oxb + t - 12)] = make_float2(sA, sB);
                }
            }
        }
        __syncthreads();

        // ---------- V2: vertical 7-sum of hs + combine + store ------------
        // thread = (out-x 0..31, segment 0..7); 6 out rows per segment
        {
            int ox  = tid & 31;
            int seg = tid >> 5;
            int ya0 = seg * 6;
            float wa[7], wb[7];
            float sA = 0.f, sB = 0.f;
#pragma unroll
            for (int k = 0; k < 7; k++) { wa[k] = 0.f; wb[k] = 0.f; }
            const int gx = x0 + ox;
            float* Ob = gOz + (size_t)ch * HWC;
#pragma unroll
            for (int t = 0; t < 12; t++) {
                int ar = ya0 + t;
                float2 h = (ar < ABR) ? pH[ar * HP2 + ox]
                                      : make_float2(0.f, 0.f);
                int k = t % 7;
                sA += h.x - wa[k]; sB += h.y - wb[k];
                wa[k] = h.x; wb[k] = h.y;
                if (t >= 6) {
                    int oy = ya0 + t - 6;
                    int gy = y0 + oy;
                    if (oy < TH && (INTERIOR || gy < HD)) {
                        int off = gy * WD + gx;
                        float q = fmaf(sA * INV49, Ib[off], sB * INV49);
                        q = fminf(fmaxf(q, 0.0f), 1.0f);
                        Ob[off] = q;
                    }
                }
            }
        }
        // No trailing sync: V2 reads pH; next V1 writes only pB (disjoint),
        // and the next post-V1 barrier orders the following pH overwrite.
    }
}

__global__ void __launch_bounds__(NT, 4)
gf_kernel(const float* __restrict__ gI,
          const float* __restrict__ gP,
          float* __restrict__ gOut) {
    extern __shared__ float2 sm2[];
    const int tid = threadIdx.x;
    const int bx = blockIdx.x, by = blockIdx.y, bz = blockIdx.z;
    const int x0 = bx * TW, y0 = by * TH;
    const float* Ib = gI + (size_t)bz * HWC;
    const float* gPz = gP + (size_t)bz * 3 * HWC;
    float* gOz = gOut + (size_t)bz * 3 * HWC;

    bool interior = (x0 >= 6) && (x0 + TW + 6 <= WD) &&
                    (y0 >= 6) && (y0 + TH + 6 <= HD);
    if (interior)
        gf_tile<true>(sm2, Ib, gPz, gOz, x0, y0, tid);
    else
        gf_tile<false>(sm2, Ib, gPz, gOz, x0, y0, tid);
}

extern "C" void kernel_launch(void* const* d_in, const int* in_sizes, int n_in,
                              void* d_out, int out_size) {
    const float* I = (const float*)d_in[0];
    const float* p = (const float*)d_in[1];
    if (n_in >= 2 && in_sizes[0] > in_sizes[1]) {  // defensive: I is smaller
        const float* t = I; I = p; p = t;
    }
    float* out = (float*)d_out;

    cudaFuncSetAttribute(gf_kernel,
                         cudaFuncAttributeMaxDynamicSharedMemorySize, SMEM_BYTES);
    dim3 grid(WD / TW, (HD + TH - 1) / TH, 8);
    gf_kernel<<<grid, NT, SMEM_BYTES>>>(I, p, out);
}

// round 11
// speedup vs baseline: 1.1436x; 1.0255x over previous
#include <cuda_runtime.h>

// Guided filter r=3, fused, tile 32x45, 4 CTAs/SM (52.6KB smem).
// R10 + widened chunks: H1a chunk=19, H1b chunk=16, V2 seg=12 rows.
// Fewer halo re-reads through the LDS crossbar; guards provably removable.

#define NT 256
#define WD 1024
#define HD 1024
#define HWC (1024 * 1024)
#define TW 32
#define TH 45
#define ABR 51            // TH + 6
#define VP2 45            // pA/pB pitch in float2
#define MP2 39            // M pitch in float2 (38 cols used)
#define HP2 33            // pH pitch in float2 (32 cols used)
#define INV49 (1.0f / 49.0f)
#define EPS_GF 1e-6f

#define OFF_PB 0
#define OFF_PA (ABR * VP2)            // 2295 (also pH)
#define OFF_M  (2 * ABR * VP2)        // 4590
#define N_F2   (2 * ABR * VP2 + ABR * MP2)   // 4590 + 1989 = 6579
#define SMEM_BYTES (N_F2 * 8)                // 52632 -> 4 CTAs/SM

template<bool INTERIOR>
__device__ __forceinline__ void gf_tile(float2* __restrict__ sm2,
                                        const float* __restrict__ Ib,
                                        const float* __restrict__ gPz,
                                        float* __restrict__ gOz,
                                        int x0, int y0, int tid) {
    float2* pB = sm2 + OFF_PB;     // (vp, vIp) vertical 7-sums
    float2* pA = sm2 + OFF_PA;     // (vI, vII) vertical 7-sums (ch0 only)
    float2* pH = sm2 + OFF_PA;     // (hsA, hsB) — aliases pA after H1a
    float2* M  = sm2 + OFF_M;      // (mean_I, 1/(var+eps)) per a-pixel

#pragma unroll
    for (int ch = 0; ch < 3; ch++) {
        const float* Pb = gPz + (size_t)ch * HWC;

        // ---------- V1: vertical 7-sums of {p, I*p} (+ {I,I*I} on ch0) ----
        // thread = (segment 0..4, v-col 0..43); 11 ab-rows per segment
        if (tid < 220) {
            int seg = tid / 44;
            int vx  = tid - seg * 44;
            int gxv = x0 + vx - 6;
            bool xok = INTERIOR || (unsigned)gxv < (unsigned)WD;
            int gyr0 = y0 + seg * 11 - 6;
            int ya0 = seg * 11;
            float iv7[7], pv7[7];
            float sI = 0.f, sII = 0.f, sp = 0.f, sIp = 0.f;
#pragma unroll
            for (int k = 0; k < 7; k++) { iv7[k] = 0.f; pv7[k] = 0.f; }
#pragma unroll
            for (int t = 0; t < 17; t++) {
                int gyr = gyr0 + t;
                float iv, pv;
                if (INTERIOR) {
                    int off = gyr * WD + gxv;
                    iv = Ib[off];
                    pv = Pb[off];
                } else {
                    iv = 0.f; pv = 0.f;
                    if (xok && (unsigned)gyr < (unsigned)HD) {
                        int off = gyr * WD + gxv;
                        iv = Ib[off];
                        pv = Pb[off];
                    }
                }
                int k = t % 7;
                float oi = iv7[k], oq = pv7[k];
                if (ch == 0) {
                    sI  += iv - oi;
                    sII += iv * iv - oi * oi;
                }
                sp  += pv - oq;
                sIp += iv * pv - oi * oq;
                iv7[k] = iv; pv7[k] = pv;
                if (t >= 6) {
                    int ar = ya0 + t - 6;
                    if (ar < ABR) {
                        if (ch == 0) pA[ar * VP2 + vx] = make_float2(sI, sII);
                        pB[ar * VP2 + vx] = make_float2(sp, sIp);
                    }
                }
            }
        }
        __syncthreads();

        // ---------- H1a (ch0 only): h-sums of (vI,vII) -> (mi, rv) --------
        // thread = (chunk 0..1 of 19 ax, row 0..50); tid < 102; no guards:
        // vx = axb + t <= 19+24 = 43 < 44; ax = axb+t-6 <= 37 < 38.
        if (ch == 0) {
            if (tid < 102) {
                int c  = tid / ABR;
                int ya = tid - c * ABR;
                int axb = c * 19;
                int row = ya * VP2;
                float w0[7], w1[7];
                float s0 = 0.f, s1 = 0.f;
#pragma unroll
                for (int k = 0; k < 7; k++) { w0[k] = 0.f; w1[k] = 0.f; }
#pragma unroll
                for (int t = 0; t < 25; t++) {
                    float2 A = pA[row + axb + t];
                    int k = t % 7;
                    s0 += A.x - w0[k]; s1 += A.y - w1[k];
                    w0[k] = A.x; w1[k] = A.y;
                    if (t >= 6) {
                        int ax = axb + t - 6;
                        float mi  = s0 * INV49;
                        float var = fmaf(s1, INV49, -mi * mi);
                        M[ya * MP2 + ax] =
                            make_float2(mi, __fdividef(1.0f, var + EPS_GF));
                    }
                }
            }
            __syncthreads();
        }

        // ---------- H1b: h-sums of (vp,vIp) -> a,b -> h-sums of a,b -------
        // thread = (chunk 0..1 of 16 out-x, row 0..50); tid < 102; no vx/ox
        // guards: vx = oxb + t <= 16+27 = 43 < 44; ox = oxb+t-12 <= 31.
        if (tid < 102) {
            int c  = tid / ABR;
            int ya = tid - c * ABR;
            int oxb = c * 16;
            int gya = y0 + ya - 3;
            bool yok = INTERIOR || (unsigned)gya < (unsigned)HD;
            int rowB = ya * VP2, rowM = ya * MP2, rowH = ya * HP2;
            float wp[7], wq[7], wa[7], wb[7];
            float s2 = 0.f, s3 = 0.f, sA = 0.f, sB = 0.f;
#pragma unroll
            for (int k = 0; k < 7; k++) {
                wp[k] = 0.f; wq[k] = 0.f; wa[k] = 0.f; wb[k] = 0.f;
            }
#pragma unroll
            for (int t = 0; t < 28; t++) {
                float2 B = pB[rowB + oxb + t];
                int k = t % 7;
                s2 += B.x - wp[k]; s3 += B.y - wq[k];
                wp[k] = B.x; wq[k] = B.y;
                if (t >= 6) {
                    int ax = oxb + t - 6;            // a-index, gx = x0+ax-3
                    float av, bv;
                    if (INTERIOR || (yok && (unsigned)(x0 + ax - 3) < (unsigned)WD)) {
                        float2 m = M[rowM + ax];
                        float mp  = s2 * INV49;
                        float mip = s3 * INV49;
                        av = (mip - m.x * mp) * m.y;
                        bv = fmaf(-av, m.x, mp);
                    } else {
                        av = 0.f; bv = 0.f;
                    }
                    sA += av - wa[k]; sB += bv - wb[k];
                    wa[k] = av; wb[k] = bv;
                    if (t >= 12)
                        pH[rowH + (oxb + t - 12)] = make_float2(sA, sB);
                }
            }
        }
        __syncthreads();

        // ---------- V2: vertical 7-sum of hs + combine + store ------------
        // thread = (out-x 0..31, segment 0..3); 12 out rows per segment
        if (tid < 128) {
            int ox  = tid & 31;
            int seg = tid >> 5;
            int ya0 = seg * 12;
            float wa[7], wb[7];
            float sA = 0.f, sB = 0.f;
#pragma unroll
            for (int k = 0; k < 7; k++) { wa[k] = 0.f; wb[k] = 0.f; }
            const int gx = x0 + ox;
            float* Ob = gOz + (size_t)ch * HWC;
#pragma unroll
            for (int t = 0; t < 18; t++) {
                int ar = ya0 + t;
                float2 h = (ar < ABR) ? pH[ar * HP2 + ox]
                                      : make_float2(0.f, 0.f);
                int k = t % 7;
                sA += h.x - wa[k]; sB += h.y - wb[k];
                wa[k] = h.x; wb[k] = h.y;
                if (t >= 6) {
                    int oy = ya0 + t - 6;
                    int gy = y0 + oy;
                    if (oy < TH && (INTERIOR || gy < HD)) {
                        int off = gy * WD + gx;
                        float q = fmaf(sA * INV49, Ib[off], sB * INV49);
                        q = fminf(fmaxf(q, 0.0f), 1.0f);
                        Ob[off] = q;
                    }
                }
            }
        }
        // No trailing sync: V2 reads pH; next V1 writes only pB (disjoint),
        // and the next post-V1 barrier orders the following pH overwrite.
    }
}

__global__ void __launch_bounds__(NT, 4)
gf_kernel(const float* __restrict__ gI,
          const float* __restrict__ gP,
          float* __restrict__ gOut) {
    extern __shared__ float2 sm2[];
    const int tid = threadIdx.x;
    const int bx = blockIdx.x, by = blockIdx.y, bz = blockIdx.z;
    const int x0 = bx * TW, y0 = by * TH;
    const float* Ib = gI + (size_t)bz * HWC;
    const float* gPz = gP + (size_t)bz * 3 * HWC;
    float* gOz = gOut + (size_t)bz * 3 * HWC;

    bool interior = (x0 >= 6) && (x0 + TW + 6 <= WD) &&
                    (y0 >= 6) && (y0 + TH + 6 <= HD);
    if (interior)
        gf_tile<true>(sm2, Ib, gPz, gOz, x0, y0, tid);
    else
        gf_tile<false>(sm2, Ib, gPz, gOz, x0, y0, tid);
}

extern "C" void kernel_launch(void* const* d_in, const int* in_sizes, int n_in,
                              void* d_out, int out_size) {
    const float* I = (const float*)d_in[0];
    const float* p = (const float*)d_in[1];
    if (n_in >= 2 && in_sizes[0] > in_sizes[1]) {  // defensive: I is smaller
        const float* t = I; I = p; p = t;
    }
    float* out = (float*)d_out;

    cudaFuncSetAttribute(gf_kernel,
                         cudaFuncAttributeMaxDynamicSharedMemorySize, SMEM_BYTES);
    dim3 grid(WD / TW, (HD + TH - 1) / TH, 8);
    gf_kernel<<<grid, NT, SMEM_BYTES>>>(I, p, out);
}

// round 16
// speedup vs baseline: 1.4972x; 1.3092x over previous
#include <cuda_runtime.h>

// Guided filter r=3, fused, tile 32x90, NT=512, 2 CTAs/SM (99KB smem).
// R11 per-thread phase loops, taller tile: halved barrier events/output,
// better vertical-halo amortization in V1.

#define NT 512
#define WD 1024
#define HD 1024
#define HWC (1024 * 1024)
#define TW 32
#define TH 90
#define ABR 96            // TH + 6
#define VP2 45            // pA/pB pitch in float2
#define MP2 39            // M pitch in float2 (38 cols used)
#define HP2 33            // pH pitch in float2 (32 cols used)
#define INV49 (1.0f / 49.0f)
#define EPS_GF 1e-6f

#define OFF_PB 0
#define OFF_PA (ABR * VP2)            // 4320 (also pH)
#define OFF_M  (2 * ABR * VP2)        // 8640
#define N_F2   (2 * ABR * VP2 + ABR * MP2)   // 8640 + 3744 = 12384
#define SMEM_BYTES (N_F2 * 8)                // 99072 -> 2 CTAs/SM

template<bool INTERIOR>
__device__ __forceinline__ void gf_tile(float2* __restrict__ sm2,
                                        const float* __restrict__ Ib,
                                        const float* __restrict__ gPz,
                                        float* __restrict__ gOz,
                                        int x0, int y0, int tid) {
    float2* pB = sm2 + OFF_PB;     // (vp, vIp) vertical 7-sums
    float2* pA = sm2 + OFF_PA;     // (vI, vII) vertical 7-sums (ch0 only)
    float2* pH = sm2 + OFF_PA;     // (hsA, hsB) — aliases pA after H1a
    float2* M  = sm2 + OFF_M;      // (mean_I, 1/(var+eps)) per a-pixel

#pragma unroll
    for (int ch = 0; ch < 3; ch++) {
        const float* Pb = gPz + (size_t)ch * HWC;

        // ---------- V1: vertical 7-sums of {p, I*p} (+ {I,I*I} on ch0) ----
        // thread = (segment 0..7, v-col 0..43); 12 ab-rows per segment
        // (8*12 = 96 = ABR exactly: no ar guard needed)
        if (tid < 352) {
            int seg = tid / 44;
            int vx  = tid - seg * 44;
            int gxv = x0 + vx - 6;
            bool xok = INTERIOR || (unsigned)gxv < (unsigned)WD;
            int gyr0 = y0 + seg * 12 - 6;
            int ya0 = seg * 12;
            float iv7[7], pv7[7];
            float sI = 0.f, sII = 0.f, sp = 0.f, sIp = 0.f;
#pragma unroll
            for (int k = 0; k < 7; k++) { iv7[k] = 0.f; pv7[k] = 0.f; }
#pragma unroll
            for (int t = 0; t < 18; t++) {
                int gyr = gyr0 + t;
                float iv, pv;
                if (INTERIOR) {
                    int off = gyr * WD + gxv;
                    iv = Ib[off];
                    pv = Pb[off];
                } else {
                    iv = 0.f; pv = 0.f;
                    if (xok && (unsigned)gyr < (unsigned)HD) {
                        int off = gyr * WD + gxv;
                        iv = Ib[off];
                        pv = Pb[off];
                    }
                }
                int k = t % 7;
                float oi = iv7[k], oq = pv7[k];
                if (ch == 0) {
                    sI  += iv - oi;
                    sII += iv * iv - oi * oi;
                }
                sp  += pv - oq;
                sIp += iv * pv - oi * oq;
                iv7[k] = iv; pv7[k] = pv;
                if (t >= 6) {
                    int ar = ya0 + t - 6;            // <= 95 < ABR always
                    if (ch == 0) pA[ar * VP2 + vx] = make_float2(sI, sII);
                    pB[ar * VP2 + vx] = make_float2(sp, sIp);
                }
            }
        }
        __syncthreads();

        // ---------- H1a (ch0 only): h-sums of (vI,vII) -> (mi, rv) --------
        // thread = (chunk 0..1 of 19 ax, row 0..95); tid < 192; no guards:
        // vx = axb + t <= 19+24 = 43 < 44; ax = axb+t-6 <= 37 < 38.
        if (ch == 0) {
            if (tid < 192) {
                int c  = tid / ABR;
                int ya = tid - c * ABR;
                int axb = c * 19;
                int row = ya * VP2;
                float w0[7], w1[7];
                float s0 = 0.f, s1 = 0.f;
#pragma unroll
                for (int k = 0; k < 7; k++) { w0[k] = 0.f; w1[k] = 0.f; }
#pragma unroll
                for (int t = 0; t < 25; t++) {
                    float2 A = pA[row + axb + t];
                    int k = t % 7;
                    s0 += A.x - w0[k]; s1 += A.y - w1[k];
                    w0[k] = A.x; w1[k] = A.y;
                    if (t >= 6) {
                        int ax = axb + t - 6;
                        float mi  = s0 * INV49;
                        float var = fmaf(s1, INV49, -mi * mi);
                        M[ya * MP2 + ax] =
                            make_float2(mi, __fdividef(1.0f, var + EPS_GF));
                    }
                }
            }
            __syncthreads();
        }

        // ---------- H1b: h-sums of (vp,vIp) -> a,b -> h-sums of a,b -------
        // thread = (chunk 0..1 of 16 out-x, row 0..95); tid < 192; no vx/ox
        // guards: vx = oxb + t <= 16+27 = 43 < 44; ox = oxb+t-12 <= 31.
        if (tid < 192) {
            int c  = tid / ABR;
            int ya = tid - c * ABR;
            int oxb = c * 16;
            int gya = y0 + ya - 3;
            bool yok = INTERIOR || (unsigned)gya < (unsigned)HD;
            int rowB = ya * VP2, rowM = ya * MP2, rowH = ya * HP2;
            float wp[7], wq[7], wa[7], wb[7];
            float s2 = 0.f, s3 = 0.f, sA = 0.f, sB = 0.f;
#pragma unroll
            for (int k = 0; k < 7; k++) {
                wp[k] = 0.f; wq[k] = 0.f; wa[k] = 0.f; wb[k] = 0.f;
            }
#pragma unroll
            for (int t = 0; t < 28; t++) {
                float2 B = pB[rowB + oxb + t];
                int k = t % 7;
                s2 += B.x - wp[k]; s3 += B.y - wq[k];
                wp[k] = B.x; wq[k] = B.y;
                if (t >= 6) {
                    int ax = oxb + t - 6;            // a-index, gx = x0+ax-3
                    float av, bv;
                    if (INTERIOR || (yok && (unsigned)(x0 + ax - 3) < (unsigned)WD)) {
                        float2 m = M[rowM + ax];
                        float mp  = s2 * INV49;
                        float mip = s3 * INV49;
                        av = (mip - m.x * mp) * m.y;
                        bv = fmaf(-av, m.x, mp);
                    } else {
                        av = 0.f; bv = 0.f;
                    }
                    sA += av - wa[k]; sB += bv - wb[k];
                    wa[k] = av; wb[k] = bv;
                    if (t >= 12)
                        pH[rowH + (oxb + t - 12)] = make_float2(sA, sB);
                }
            }
        }
        __syncthreads();

        // ---------- V2: vertical 7-sum of hs + combine + store ------------
        // thread = (out-x 0..31, segment 0..7); 12 out rows per segment
        if (tid < 256) {
            int ox  = tid & 31;
            int seg = tid >> 5;
            int ya0 = seg * 12;
            float wa[7], wb[7];
            float sA = 0.f, sB = 0.f;
#pragma unroll
            for (int k = 0; k < 7; k++) { wa[k] = 0.f; wb[k] = 0.f; }
            const int gx = x0 + ox;
            float* Ob = gOz + (size_t)ch * HWC;
#pragma unroll
            for (int t = 0; t < 18; t++) {
                int ar = ya0 + t;
                float2 h = (ar < ABR) ? pH[ar * HP2 + ox]
                                      : make_float2(0.f, 0.f);
                int k = t % 7;
                sA += h.x - wa[k]; sB += h.y - wb[k];
                wa[k] = h.x; wb[k] = h.y;
                if (t >= 6) {
                    int oy = ya0 + t - 6;
                    int gy = y0 + oy;
                    if (oy < TH && (INTERIOR || gy < HD)) {
                        int off = gy * WD + gx;
                        float q = fmaf(sA * INV49, Ib[off], sB * INV49);
                        q = fminf(fmaxf(q, 0.0f), 1.0f);
                        Ob[off] = q;
                    }
                }
            }
        }
        // No trailing sync: V2 reads pH; next V1 writes only pB (disjoint),
        // and the next post-V1 barrier orders the following pH overwrite.
    }
}

__global__ void __launch_bounds__(NT, 2)
gf_kernel(const float* __restrict__ gI,
          const float* __restrict__ gP,
          float* __restrict__ gOut) {
    extern __shared__ float2 sm2[];
    const int tid = threadIdx.x;
    const int bx = blockIdx.x, by = blockIdx.y, bz = blockIdx.z;
    const int x0 = bx * TW, y0 = by * TH;
    const float* Ib = gI + (size_t)bz * HWC;
    const float* gPz = gP + (size_t)bz * 3 * HWC;
    float* gOz = gOut + (size_t)bz * 3 * HWC;

    bool interior = (x0 >= 6) && (x0 + TW + 6 <= WD) &&
                    (y0 >= 6) && (y0 + TH + 6 <= HD);
    if (interior)
        gf_tile<true>(sm2, Ib, gPz, gOz, x0, y0, tid);
    else
        gf_tile<false>(sm2, Ib, gPz, gOz, x0, y0, tid);
}

extern "C" void kernel_launch(void* const* d_in, const int* in_sizes, int n_in,
                              void* d_out, int out_size) {
    const float* I = (const float*)d_in[0];
    const float* p = (const float*)d_in[1];
    if (n_in >= 2 && in_sizes[0] > in_sizes[1]) {  // defensive: I is smaller
        const float* t = I; I = p; p = t;
    }
    float* out = (float*)d_out;

    cudaFuncSetAttribute(gf_kernel,
                         cudaFuncAttributeMaxDynamicSharedMemorySize, SMEM_BYTES);
    dim3 grid(WD / TW, (HD + TH - 1) / TH, 8);
    gf_kernel<<<grid, NT, SMEM_BYTES>>>(I, p, out);
}